// round 13
// baseline (speedup 1.0000x reference)
#include <cuda_runtime.h>
#include <math.h>
#include <stdint.h>

#define Bq  16
#define Cc  256
#define NHh 8
#define KDd 32
#define Nn  4096
#define Hh  64
#define Ww  64
#define AGg 64

// ---------------- scratch (device globals; no allocation allowed) -----------
__device__ float g_qkv[(size_t)Bq * 768 * Nn];
__device__ float g_a[Bq * NHh * KDd * AGg];
__device__ float g_pb[NHh * AGg * Nn];
__device__ float g_ab[NHh * AGg * Nn];
__device__ float g_attn[Bq * NHh * AGg * KDd];
__device__ float g_out[(size_t)Bq * Cc * Nn];
__device__ __align__(256) float g_xr[(size_t)Bq * Cc * Nn];
__device__ __align__(256) float g_wq[768 * 256];
__device__ __align__(256) float g_wp[256 * 256];
__device__ float g_p1acc[128 * 4 * AGg * KDd];
__device__ float g_p1m[128 * 4 * AGg];
__device__ float g_p1l[128 * 4 * AGg];

__device__ __forceinline__ uint32_t f2tf32(float f) {
    uint32_t r;
    asm("cvt.rna.tf32.f32 %0, %1;" : "=r"(r) : "f"(f));
    return r;
}
__device__ __forceinline__ uint32_t smem_u32(const void* p) {
    uint32_t a;
    asm("{ .reg .u64 t; cvta.to.shared.u64 t, %1; cvt.u32.u64 %0, t; }"
        : "=r"(a) : "l"(p));
    return a;
}

// ---------------- tf32 pre-rounding pass (rna), float4 ----------------------
__global__ __launch_bounds__(256) void round_tf32_kernel(
    const float* __restrict__ in, float* __restrict__ out, int n)
{
    int i = (blockIdx.x * 256 + threadIdx.x) * 4;
    if (i >= n) return;
    float4 v = *(const float4*)(in + i);
    float4 o;
    o.x = __uint_as_float(f2tf32(v.x));
    o.y = __uint_as_float(f2tf32(v.y));
    o.z = __uint_as_float(f2tf32(v.z));
    o.w = __uint_as_float(f2tf32(v.w));
    *(float4*)(out + i) = o;
}

// ======================= tf32 mma.sync GEMM + BN (R10 config) ================
#define AS_STRIDE 36
#define BS_STRIDE 136
#define AFLOATS (128 * AS_STRIDE)
#define BFLOATS (32 * BS_STRIDE)
#define ABYTES (AFLOATS * 4)
#define STAGE_FLOATS (AFLOATS + BFLOATS)
#define STAGE_BYTES (STAGE_FLOATS * 4)
#define GEMM_SMEM (3 * STAGE_BYTES)

__device__ __forceinline__ void mma_tf32(float* c, const uint32_t* a, const uint32_t* b) {
    asm volatile(
        "mma.sync.aligned.m16n8k8.row.col.f32.tf32.tf32.f32 "
        "{%0,%1,%2,%3}, {%4,%5,%6,%7}, {%8,%9}, {%0,%1,%2,%3};"
        : "+f"(c[0]), "+f"(c[1]), "+f"(c[2]), "+f"(c[3])
        : "r"(a[0]), "r"(a[1]), "r"(a[2]), "r"(a[3]), "r"(b[0]), "r"(b[1]));
}

__global__ __launch_bounds__(256, 2) void gemm_ca(
    const float* __restrict__ X, const float* __restrict__ Wm,
    const float* __restrict__ bnp, float* __restrict__ Y,
    int M, int K, int NN)
{
    extern __shared__ float sm[];
    uint32_t sb = smem_u32(sm);
    int b = blockIdx.z, mBase = blockIdx.y * 128, nBase = blockIdx.x * 128;
    const float* Xb = X + (size_t)b * K * NN;
    float* Yb = Y + (size_t)b * M * NN;
    int tid = threadIdx.x, lane = tid & 31, wid = tid >> 5;
    int woffM = (wid >> 2) * 64, woffN = (wid & 3) * 32;

    int am = tid >> 1, ak = (tid & 1) * 16;
    int bk = tid >> 3, bn = (tid & 7) * 16;

    const float* wsrc0 = Wm + (size_t)(mBase + am) * K + ak;
    const float* xsrc0 = Xb + (size_t)bk * NN + nBase + bn;
    uint32_t adst_base = sb + (uint32_t)(am * AS_STRIDE + ak) * 4;
    uint32_t bdst_base = sb + ABYTES + (uint32_t)(bk * BS_STRIDE + bn) * 4;

    int lrow = lane & 15;
    int lcol = (lane >> 4) * 4;

    float c[4][4][4];
    #pragma unroll
    for (int mt = 0; mt < 4; mt++)
        #pragma unroll
        for (int nt = 0; nt < 4; nt++)
            #pragma unroll
            for (int r = 0; r < 4; r++) c[mt][nt][r] = 0.f;

    auto issue = [&](int ch, int buf) {
        const float* ws = wsrc0 + ch * 32;
        uint32_t ad = adst_base + buf * STAGE_BYTES;
        #pragma unroll
        for (int f = 0; f < 4; f++)
            asm volatile("cp.async.cg.shared.global [%0], [%1], 16;"
                :: "r"(ad + f * 16), "l"(ws + f * 4));
        const float* xs = xsrc0 + (size_t)(ch * 32) * NN;
        uint32_t bd = bdst_base + buf * STAGE_BYTES;
        #pragma unroll
        for (int f = 0; f < 4; f++)
            asm volatile("cp.async.cg.shared.global [%0], [%1], 16;"
                :: "r"(bd + f * 16), "l"(xs + f * 4));
        asm volatile("cp.async.commit_group;");
    };

    int nch = K >> 5;
    issue(0, 0);
    if (nch > 1) issue(1, 1);

    for (int ch = 0; ch < nch; ch++) {
        if (ch + 1 < nch) asm volatile("cp.async.wait_group 1;");
        else              asm volatile("cp.async.wait_group 0;");
        __syncthreads();
        if (ch + 2 < nch) issue(ch + 2, (ch + 2) % 3);

        uint32_t abase = sb + (ch % 3) * STAGE_BYTES;
        const float* bs = sm + (ch % 3) * STAGE_FLOATS + AFLOATS;

        #pragma unroll
        for (int ks = 0; ks < 4; ks++) {
            uint32_t af[4][4], bf[4][2];
            #pragma unroll
            for (int mt = 0; mt < 4; mt++) {
                uint32_t a_addr = abase +
                    (uint32_t)((woffM + mt * 16 + lrow) * AS_STRIDE + ks * 8 + lcol) * 4;
                asm volatile(
                    "ldmatrix.sync.aligned.m8n8.x4.shared.b16 {%0,%1,%2,%3}, [%4];"
                    : "=r"(af[mt][0]), "=r"(af[mt][1]), "=r"(af[mt][2]), "=r"(af[mt][3])
                    : "r"(a_addr));
            }
            int br = ks * 8 + (lane & 3);
            int bc = woffN + (lane >> 2);
            #pragma unroll
            for (int nt = 0; nt < 4; nt++) {
                const float* bb = bs + br * BS_STRIDE + bc + nt * 8;
                bf[nt][0] = __float_as_uint(bb[0]);
                bf[nt][1] = __float_as_uint(bb[4 * BS_STRIDE]);
            }
            #pragma unroll
            for (int mt = 0; mt < 4; mt++)
                #pragma unroll
                for (int nt = 0; nt < 4; nt++)
                    mma_tf32(c[mt][nt], af[mt], bf[nt]);
        }
    }

    #pragma unroll
    for (int mt = 0; mt < 4; mt++) {
        int r0 = mBase + woffM + mt * 16 + (lane >> 2);
        int r1 = r0 + 8;
        float g0 = bnp[r0], b0 = bnp[M + r0], m0 = bnp[2 * M + r0], v0 = bnp[3 * M + r0];
        float g1 = bnp[r1], b1 = bnp[M + r1], m1 = bnp[2 * M + r1], v1 = bnp[3 * M + r1];
        float inv0 = g0 * rsqrtf(v0 + 1e-5f), bias0 = b0 - m0 * inv0;
        float inv1 = g1 * rsqrtf(v1 + 1e-5f), bias1 = b1 - m1 * inv1;
        #pragma unroll
        for (int nt = 0; nt < 4; nt++) {
            int n = nBase + woffN + nt * 8 + 2 * (lane & 3);
            float2 o0, o1;
            o0.x = c[mt][nt][0] * inv0 + bias0;
            o0.y = c[mt][nt][1] * inv0 + bias0;
            o1.x = c[mt][nt][2] * inv1 + bias1;
            o1.y = c[mt][nt][3] * inv1 + bias1;
            *(float2*)(Yb + (size_t)r0 * NN + n) = o0;
            *(float2*)(Yb + (size_t)r1 * NN + n) = o1;
        }
    }
}

// ---------------- pooling ----------------------------------------------------
__global__ __launch_bounds__(256) void pool_kernel()
{
    int b = blockIdx.y, g = blockIdx.x, c = threadIdx.x;
    int gh = g >> 3, gw = g & 7;
    float s = 0.f;
    for (int hh = 0; hh < 8; hh++) {
        int h = gh * 8 + hh;
        for (int ww2 = 0; ww2 < 8; ww2++) {
            int w = gw * 8 + ww2;
            int flat = (h * Ww + w) * Cc + c;
            int nh = flat >> 17;
            int kd = (flat >> 12) & 31;
            int n  = flat & 4095;
            s += g_qkv[((size_t)(b * 768 + nh * 96 + kd)) * Nn + n];
        }
    }
    g_a[((b * NHh + (c >> 5)) * KDd + (c & 31)) * AGg + g] = s * (1.f / 64.f);
}

// ---------------- bilinear 7x7 -> 64x64 --------------------------------------
__device__ __forceinline__ float bilin7(const float* __restrict__ p, int oy, int ox)
{
    float uy = (oy + 0.5f) * (7.f / 64.f) - 0.5f;
    float ux = (ox + 0.5f) * (7.f / 64.f) - 0.5f;
    float fy = floorf(uy), fx = floorf(ux);
    int y0 = (int)fy, x0 = (int)fx;
    float ty = uy - fy, tx = ux - fx;
    int y0c = min(6, max(0, y0)),     y1c = min(6, max(0, y0 + 1));
    int x0c = min(6, max(0, x0)),     x1c = min(6, max(0, x0 + 1));
    float v00 = p[y0c * 7 + x0c], v01 = p[y0c * 7 + x1c];
    float v10 = p[y1c * 7 + x0c], v11 = p[y1c * 7 + x1c];
    return (v00 * (1.f - tx) + v01 * tx) * (1.f - ty)
         + (v10 * (1.f - tx) + v11 * tx) * ty;
}

// merged pb + ab
__global__ __launch_bounds__(256) void bias_kernel(
    const float* __restrict__ an, const float* __restrict__ ah, const float* __restrict__ aw,
    const float* __restrict__ na, const float* __restrict__ ha, const float* __restrict__ wa)
{
    int z = blockIdx.z, g = blockIdx.y;
    int n = blockIdx.x * 256 + threadIdx.x;
    int h = n >> 6, w = n & 63;
    if (z < 8) {
        int nh = z;
        float v = bilin7(an + (nh * AGg + g) * 49, h, w)
                + ah[(nh * AGg + g) * Hh + h] + aw[(nh * AGg + g) * Ww + w];
        g_pb[(size_t)(nh * AGg + g) * Nn + n] = v;
    } else {
        int nh = z - 8;
        float v = bilin7(na + (nh * AGg + g) * 49, h, w)
                + ha[(nh * Hh + h) * AGg + g] + wa[(nh * Ww + w) * AGg + g];
        g_ab[(size_t)(nh * AGg + g) * Nn + n] = v;
    }
}

// ---------------- attention-1 split: QK via mma.sync tf32 --------------------
// grid (4 splits, 128 bh), 256 threads, 8 warps.
// Warp tile of S[64g][64n]: warp w -> g rows (w&3)*16..+15, n cols (w>>2)*32..+31
__global__ __launch_bounds__(256) void attn1_split()
{
    int s = blockIdx.x;
    int bh = blockIdx.y; int b = bh >> 3, nh = bh & 7;
    __shared__ __align__(16) float aT_s[64][36];   // a^T[g][kd], tf32-rounded
    __shared__ __align__(16) float S[64][68];
    __shared__ float k_s[32][65];                  // tf32-rounded
    __shared__ float v_s[64][33];
    __shared__ float m_sh[64], l_sh[64], fact[64];
    int t = threadIdx.x;
    int lane = t & 31, wid = t >> 5;

    for (int i = t; i < 2048; i += 256) {
        int kd = i >> 6, g = i & 63;
        aT_s[g][kd] = __uint_as_float(f2tf32(g_a[((b * NHh + nh) * KDd) * AGg + i]));
    }
    if (t < 64) { m_sh[t] = -1e30f; l_sh[t] = 0.f; }
    __syncthreads();

    int woffG = (wid & 3) * 16;
    int woffN2 = (wid >> 2) * 32;

    // A fragments (loop-invariant): m16k8 row-major mapping
    uint32_t a_frag[4][4];
    #pragma unroll
    for (int ks = 0; ks < 4; ks++) {
        const float* ab = &aT_s[woffG + (lane >> 2)][ks * 8 + (lane & 3)];
        a_frag[ks][0] = __float_as_uint(ab[0]);
        a_frag[ks][1] = __float_as_uint(ab[8 * 36]);
        a_frag[ks][2] = __float_as_uint(ab[4]);
        a_frag[ks][3] = __float_as_uint(ab[8 * 36 + 4]);
    }

    const float* kbase = g_qkv + (size_t)(b * 768 + nh * 96 + 32) * Nn;
    const float* vbase = g_qkv + (size_t)(b * 768 + nh * 96 + 64) * Nn;
    const float* pbase = g_pb + (size_t)nh * AGg * Nn;
    const float scale = 0.17677669529663687f;

    float acc[8];
    #pragma unroll
    for (int j = 0; j < 8; j++) acc[j] = 0.f;

    int nStart = s * 1024, nEnd = nStart + 1024;

    for (int n0 = nStart; n0 < nEnd; n0 += 64) {
        for (int i = t; i < 2048; i += 256) {
            int ck = i >> 6, cn = i & 63;
            k_s[ck][cn] = __uint_as_float(f2tf32(kbase[(size_t)ck * Nn + n0 + cn]));
            v_s[cn][ck] = vbase[(size_t)ck * Nn + n0 + cn];
        }
        __syncthreads();

        // ---- logits via mma: S_tile[16g x 32n] per warp
        {
            float c[4][4];
            #pragma unroll
            for (int nt = 0; nt < 4; nt++)
                #pragma unroll
                for (int r = 0; r < 4; r++) c[nt][r] = 0.f;
            #pragma unroll
            for (int ks = 0; ks < 4; ks++) {
                uint32_t bf[4][2];
                int br = ks * 8 + (lane & 3);
                int bc = woffN2 + (lane >> 2);
                #pragma unroll
                for (int nt = 0; nt < 4; nt++) {
                    bf[nt][0] = __float_as_uint(k_s[br][bc + nt * 8]);
                    bf[nt][1] = __float_as_uint(k_s[br + 4][bc + nt * 8]);
                }
                #pragma unroll
                for (int nt = 0; nt < 4; nt++)
                    mma_tf32(c[nt], a_frag[ks], bf[nt]);
            }
            int g0 = woffG + (lane >> 2);
            #pragma unroll
            for (int nt = 0; nt < 4; nt++) {
                int nl = woffN2 + nt * 8 + 2 * (lane & 3);
                *(float2*)&S[g0][nl]     = make_float2(c[nt][0], c[nt][1]);
                *(float2*)&S[g0 + 8][nl] = make_float2(c[nt][2], c[nt][3]);
            }
        }
        __syncthreads();

        // ---- online softmax (scale + pb applied here, fp32)
        #pragma unroll
        for (int j = 0; j < 8; j++) {
            int g = wid * 8 + j;
            const float* pbr = pbase + (size_t)g * Nn + n0;
            float v0 = S[g][lane] * scale + pbr[lane];
            float v1 = S[g][lane + 32] * scale + pbr[lane + 32];
            float mx = fmaxf(v0, v1);
            #pragma unroll
            for (int o = 16; o > 0; o >>= 1) mx = fmaxf(mx, __shfl_xor_sync(~0u, mx, o));
            float mold = m_sh[g];
            float mnew = fmaxf(mold, mx);
            float e0 = __expf(v0 - mnew), e1 = __expf(v1 - mnew);
            S[g][lane] = e0; S[g][lane + 32] = e1;
            float sum = e0 + e1;
            #pragma unroll
            for (int o = 16; o > 0; o >>= 1) sum += __shfl_xor_sync(~0u, sum, o);
            if (lane == 0) {
                float f = __expf(mold - mnew);
                l_sh[g] = l_sh[g] * f + sum;
                m_sh[g] = mnew;
                fact[g] = f;
            }
        }
        __syncthreads();

        // ---- PV accumulate (unchanged)
        {
            float a2[8];
            #pragma unroll
            for (int j = 0; j < 8; j++) a2[j] = acc[j] * fact[wid * 8 + j];
            #pragma unroll 4
            for (int nb = 0; nb < 64; nb += 4) {
                float vv0 = v_s[nb + 0][lane], vv1 = v_s[nb + 1][lane];
                float vv2 = v_s[nb + 2][lane], vv3 = v_s[nb + 3][lane];
                #pragma unroll
                for (int j = 0; j < 8; j++) {
                    float4 s4 = *(const float4*)&S[wid * 8 + j][nb];
                    a2[j] += s4.x * vv0 + s4.y * vv1 + s4.z * vv2 + s4.w * vv3;
                }
            }
            #pragma unroll
            for (int j = 0; j < 8; j++) acc[j] = a2[j];
        }
        __syncthreads();
    }
    #pragma unroll
    for (int j = 0; j < 8; j++) {
        int g = wid * 8 + j;
        int base = (bh * 4 + s) * AGg + g;
        g_p1acc[base * KDd + lane] = acc[j];
        if (lane == 0) { g_p1m[base] = m_sh[g]; g_p1l[base] = l_sh[g]; }
    }
}

// ---------------- attention-1 reduce over splits ------------------------------
__global__ __launch_bounds__(256) void attn1_reduce()
{
    int bh = blockIdx.x;
    int t = threadIdx.x;
    for (int i = t; i < AGg * KDd; i += 256) {
        int g = i >> 5, kd = i & 31;
        float m0 = g_p1m[(bh * 4 + 0) * AGg + g];
        float m1 = g_p1m[(bh * 4 + 1) * AGg + g];
        float m2 = g_p1m[(bh * 4 + 2) * AGg + g];
        float m3 = g_p1m[(bh * 4 + 3) * AGg + g];
        float M = fmaxf(fmaxf(m0, m1), fmaxf(m2, m3));
        float f0 = __expf(m0 - M), f1 = __expf(m1 - M);
        float f2 = __expf(m2 - M), f3 = __expf(m3 - M);
        float L = g_p1l[(bh * 4 + 0) * AGg + g] * f0
                + g_p1l[(bh * 4 + 1) * AGg + g] * f1
                + g_p1l[(bh * 4 + 2) * AGg + g] * f2
                + g_p1l[(bh * 4 + 3) * AGg + g] * f3;
        float V = g_p1acc[((bh * 4 + 0) * AGg + g) * KDd + kd] * f0
                + g_p1acc[((bh * 4 + 1) * AGg + g) * KDd + kd] * f1
                + g_p1acc[((bh * 4 + 2) * AGg + g) * KDd + kd] * f2
                + g_p1acc[((bh * 4 + 3) * AGg + g) * KDd + kd] * f3;
        g_attn[(bh * AGg + g) * KDd + kd] = V / L;
    }
}

// ------- fused attention-2 + depthwise pe conv + BN (R10 version) -------------
__global__ __launch_bounds__(128) void attn2_pe_kernel(
    const float* __restrict__ pw, const float* __restrict__ pebn)
{
    int b = blockIdx.z, nh = blockIdx.y;
    int n = blockIdx.x * 128 + threadIdx.x;
    int t = threadIdx.x;
    int h = n >> 6, w = n & 63;
    __shared__ __align__(16) float a_s[32][64];
    __shared__ __align__(16) float at_s[64][32];
    __shared__ float pw_s[32][9];
    __shared__ float inv_s[32], bias_s[32];
    for (int i = t; i < 2048; i += 128) {
        a_s[i >> 6][i & 63]  = g_a[((b * NHh + nh) * KDd) * AGg + i];
        at_s[i >> 5][i & 31] = g_attn[((b * NHh + nh) * AGg) * KDd + i];
    }
    for (int i = t; i < 288; i += 128)
        pw_s[i / 9][i % 9] = pw[(nh * 32) * 9 + i];
    if (t < 32) {
        int c = nh * 32 + t;
        float gg = pebn[c], bb = pebn[Cc + c], mm = pebn[2 * Cc + c], vv = pebn[3 * Cc + c];
        float inv = gg * rsqrtf(vv + 1e-5f);
        inv_s[t] = inv;
        bias_s[t] = bb - mm * inv;
    }
    __syncthreads();

    float msk[9];
    int off[9];
    {
        int j = 0;
        #pragma unroll
        for (int dy = -1; dy <= 1; dy++)
            #pragma unroll
            for (int dx = -1; dx <= 1; dx++, j++) {
                int hy = h + dy, wx = w + dx;
                bool ok = ((unsigned)hy < 64u) && ((unsigned)wx < 64u);
                msk[j] = ok ? 1.f : 0.f;
                off[j] = ok ? (dy * 64 + dx) : 0;
            }
    }

    const float scale = 0.17677669529663687f;
    float lg[64];
    #pragma unroll
    for (int g = 0; g < 64; g++) lg[g] = 0.f;
    {
        const float* qb = g_qkv + (size_t)(b * 768 + nh * 96) * Nn + n;
        #pragma unroll
        for (int kd = 0; kd < 32; kd++) {
            float qv = qb[(size_t)kd * Nn];
            const float4* arow = (const float4*)&a_s[kd][0];
            #pragma unroll
            for (int g4 = 0; g4 < 16; g4++) {
                float4 a4 = arow[g4];
                lg[g4 * 4 + 0] += qv * a4.x;
                lg[g4 * 4 + 1] += qv * a4.y;
                lg[g4 * 4 + 2] += qv * a4.z;
                lg[g4 * 4 + 3] += qv * a4.w;
            }
        }
    }
    #pragma unroll
    for (int g = 0; g < 64; g++)
        lg[g] = lg[g] * scale + g_ab[(size_t)(nh * AGg + g) * Nn + n];

    float mx = -1e30f;
    #pragma unroll
    for (int g = 0; g < 64; g++) mx = fmaxf(mx, lg[g]);
    float sum = 0.f;
    #pragma unroll
    for (int g = 0; g < 64; g++) { lg[g] = __expf(lg[g] - mx); sum += lg[g]; }
    float invs = 1.f / sum;

    float acc[32];
    #pragma unroll
    for (int kd = 0; kd < 32; kd++) acc[kd] = 0.f;
    #pragma unroll
    for (int g = 0; g < 64; g++) {
        float p = lg[g];
        const float4* trow = (const float4*)&at_s[g][0];
        #pragma unroll
        for (int k4 = 0; k4 < 8; k4++) {
            float4 t4 = trow[k4];
            acc[k4 * 4 + 0] += p * t4.x;
            acc[k4 * 4 + 1] += p * t4.y;
            acc[k4 * 4 + 2] += p * t4.z;
            acc[k4 * 4 + 3] += p * t4.w;
        }
    }

    const float* vhead = g_qkv + (size_t)(b * 768 + nh * 96 + 64) * Nn + n;
    #pragma unroll 4
    for (int kd = 0; kd < 32; kd++) {
        const float* vb = vhead + (size_t)kd * Nn;
        float conv = 0.f;
        #pragma unroll
        for (int j = 0; j < 9; j++)
            conv += msk[j] * vb[off[j]] * pw_s[kd][j];
        float o = acc[kd] * invs + conv * inv_s[kd] + bias_s[kd];
        g_out[((size_t)(b * Cc + nh * KDd + kd)) * Nn + n] =
            __uint_as_float(f2tf32(o));
    }
}

// -----------------------------------------------------------------------------
extern "C" void kernel_launch(void* const* d_in, const int* in_sizes, int n_in,
                              void* d_out, int out_size)
{
    const float* x       = (const float*)d_in[0];
    const float* qkv_w   = (const float*)d_in[1];
    const float* qkv_bn  = (const float*)d_in[2];
    const float* pe_w    = (const float*)d_in[3];
    const float* pe_bn   = (const float*)d_in[4];
    const float* proj_w  = (const float*)d_in[5];
    const float* proj_bn = (const float*)d_in[6];
    const float* an_bias = (const float*)d_in[7];
    const float* na_bias = (const float*)d_in[8];
    const float* ah_bias = (const float*)d_in[9];
    const float* aw_bias = (const float*)d_in[10];
    const float* ha_bias = (const float*)d_in[11];
    const float* wa_bias = (const float*)d_in[12];
    float* out = (float*)d_out;

    float *qkv_ptr, *out_ptr, *xr_ptr, *wq_ptr, *wp_ptr;
    cudaGetSymbolAddress((void**)&qkv_ptr, g_qkv);
    cudaGetSymbolAddress((void**)&out_ptr, g_out);
    cudaGetSymbolAddress((void**)&xr_ptr,  g_xr);
    cudaGetSymbolAddress((void**)&wq_ptr,  g_wq);
    cudaGetSymbolAddress((void**)&wp_ptr,  g_wp);

    cudaFuncSetAttribute(gemm_ca, cudaFuncAttributeMaxDynamicSharedMemorySize,
                         GEMM_SMEM);

    // 0. tf32 pre-rounding (rna) of GEMM inputs
    round_tf32_kernel<<<16384, 256>>>(x, xr_ptr, Bq * Cc * Nn);
    round_tf32_kernel<<<192, 256>>>(qkv_w, wq_ptr, 768 * 256);
    round_tf32_kernel<<<64, 256>>>(proj_w, wp_ptr, 256 * 256);

    // 1. qkv GEMM + BN
    gemm_ca<<<dim3(32, 6, 16), 256, GEMM_SMEM>>>(xr_ptr, wq_ptr, qkv_bn, qkv_ptr, 768, 256, 4096);
    // 2. pooling -> a
    pool_kernel<<<dim3(64, 16), 256>>>();
    // 3. bias maps (merged)
    bias_kernel<<<dim3(16, 64, 16), 256>>>(an_bias, ah_bias, aw_bias,
                                           na_bias, ha_bias, wa_bias);
    // 4. attention-1: split (QK via mma) + reduce
    attn1_split<<<dim3(4, 128), 256>>>();
    attn1_reduce<<<128, 256>>>();
    // 5. fused attention-2 + pe conv + BN (R10 version)
    attn2_pe_kernel<<<dim3(32, 8, 16), 128>>>(pe_w, pe_bn);
    // 6. proj GEMM + BN
    gemm_ca<<<dim3(32, 2, 16), 256, GEMM_SMEM>>>(out_ptr, wp_ptr, proj_bn, out, 256, 256, 4096);
}

// round 14
// speedup vs baseline: 1.4467x; 1.4467x over previous
#include <cuda_runtime.h>
#include <math.h>
#include <stdint.h>

#define Bq  16
#define Cc  256
#define NHh 8
#define KDd 32
#define Nn  4096
#define Hh  64
#define Ww  64
#define AGg 64

// ---------------- scratch (device globals; no allocation allowed) -----------
__device__ float g_qkv[(size_t)Bq * 768 * Nn];
__device__ float g_a[Bq * NHh * KDd * AGg];
__device__ float g_pb[NHh * AGg * Nn];
__device__ float g_ab[NHh * AGg * Nn];
__device__ float g_attn[Bq * NHh * AGg * KDd];
__device__ float g_out[(size_t)Bq * Cc * Nn];
__device__ __align__(256) float g_xr[(size_t)Bq * Cc * Nn];
__device__ __align__(256) float g_wq[768 * 256];
__device__ __align__(256) float g_wp[256 * 256];
__device__ float g_p1acc[128 * 4 * AGg * KDd];
__device__ float g_p1m[128 * 4 * AGg];
__device__ float g_p1l[128 * 4 * AGg];

__device__ __forceinline__ uint32_t f2tf32(float f) {
    uint32_t r;
    asm("cvt.rna.tf32.f32 %0, %1;" : "=r"(r) : "f"(f));
    return r;
}
__device__ __forceinline__ uint32_t smem_u32(const void* p) {
    uint32_t a;
    asm("{ .reg .u64 t; cvta.to.shared.u64 t, %1; cvt.u32.u64 %0, t; }"
        : "=r"(a) : "l"(p));
    return a;
}

// ---------------- tf32 pre-rounding pass (rna), float4 ----------------------
__global__ __launch_bounds__(256) void round_tf32_kernel(
    const float* __restrict__ in, float* __restrict__ out, int n)
{
    int i = (blockIdx.x * 256 + threadIdx.x) * 4;
    if (i >= n) return;
    float4 v = *(const float4*)(in + i);
    float4 o;
    o.x = __uint_as_float(f2tf32(v.x));
    o.y = __uint_as_float(f2tf32(v.y));
    o.z = __uint_as_float(f2tf32(v.z));
    o.w = __uint_as_float(f2tf32(v.w));
    *(float4*)(out + i) = o;
}

// ======================= tf32 mma.sync GEMM + BN (R10 config) ================
#define AS_STRIDE 36
#define BS_STRIDE 136
#define AFLOATS (128 * AS_STRIDE)
#define BFLOATS (32 * BS_STRIDE)
#define ABYTES (AFLOATS * 4)
#define STAGE_FLOATS (AFLOATS + BFLOATS)
#define STAGE_BYTES (STAGE_FLOATS * 4)
#define GEMM_SMEM (3 * STAGE_BYTES)

__device__ __forceinline__ void mma_tf32(float* c, const uint32_t* a, const uint32_t* b) {
    asm volatile(
        "mma.sync.aligned.m16n8k8.row.col.f32.tf32.tf32.f32 "
        "{%0,%1,%2,%3}, {%4,%5,%6,%7}, {%8,%9}, {%0,%1,%2,%3};"
        : "+f"(c[0]), "+f"(c[1]), "+f"(c[2]), "+f"(c[3])
        : "r"(a[0]), "r"(a[1]), "r"(a[2]), "r"(a[3]), "r"(b[0]), "r"(b[1]));
}

__global__ __launch_bounds__(256, 2) void gemm_ca(
    const float* __restrict__ X, const float* __restrict__ Wm,
    const float* __restrict__ bnp, float* __restrict__ Y,
    int M, int K, int NN)
{
    extern __shared__ float sm[];
    uint32_t sb = smem_u32(sm);
    int b = blockIdx.z, mBase = blockIdx.y * 128, nBase = blockIdx.x * 128;
    const float* Xb = X + (size_t)b * K * NN;
    float* Yb = Y + (size_t)b * M * NN;
    int tid = threadIdx.x, lane = tid & 31, wid = tid >> 5;
    int woffM = (wid >> 2) * 64, woffN = (wid & 3) * 32;

    int am = tid >> 1, ak = (tid & 1) * 16;
    int bk = tid >> 3, bn = (tid & 7) * 16;

    const float* wsrc0 = Wm + (size_t)(mBase + am) * K + ak;
    const float* xsrc0 = Xb + (size_t)bk * NN + nBase + bn;
    uint32_t adst_base = sb + (uint32_t)(am * AS_STRIDE + ak) * 4;
    uint32_t bdst_base = sb + ABYTES + (uint32_t)(bk * BS_STRIDE + bn) * 4;

    int lrow = lane & 15;
    int lcol = (lane >> 4) * 4;

    float c[4][4][4];
    #pragma unroll
    for (int mt = 0; mt < 4; mt++)
        #pragma unroll
        for (int nt = 0; nt < 4; nt++)
            #pragma unroll
            for (int r = 0; r < 4; r++) c[mt][nt][r] = 0.f;

    auto issue = [&](int ch, int buf) {
        const float* ws = wsrc0 + ch * 32;
        uint32_t ad = adst_base + buf * STAGE_BYTES;
        #pragma unroll
        for (int f = 0; f < 4; f++)
            asm volatile("cp.async.cg.shared.global [%0], [%1], 16;"
                :: "r"(ad + f * 16), "l"(ws + f * 4));
        const float* xs = xsrc0 + (size_t)(ch * 32) * NN;
        uint32_t bd = bdst_base + buf * STAGE_BYTES;
        #pragma unroll
        for (int f = 0; f < 4; f++)
            asm volatile("cp.async.cg.shared.global [%0], [%1], 16;"
                :: "r"(bd + f * 16), "l"(xs + f * 4));
        asm volatile("cp.async.commit_group;");
    };

    int nch = K >> 5;
    issue(0, 0);
    if (nch > 1) issue(1, 1);

    for (int ch = 0; ch < nch; ch++) {
        if (ch + 1 < nch) asm volatile("cp.async.wait_group 1;");
        else              asm volatile("cp.async.wait_group 0;");
        __syncthreads();
        if (ch + 2 < nch) issue(ch + 2, (ch + 2) % 3);

        uint32_t abase = sb + (ch % 3) * STAGE_BYTES;
        const float* bs = sm + (ch % 3) * STAGE_FLOATS + AFLOATS;

        #pragma unroll
        for (int ks = 0; ks < 4; ks++) {
            uint32_t af[4][4], bf[4][2];
            #pragma unroll
            for (int mt = 0; mt < 4; mt++) {
                uint32_t a_addr = abase +
                    (uint32_t)((woffM + mt * 16 + lrow) * AS_STRIDE + ks * 8 + lcol) * 4;
                asm volatile(
                    "ldmatrix.sync.aligned.m8n8.x4.shared.b16 {%0,%1,%2,%3}, [%4];"
                    : "=r"(af[mt][0]), "=r"(af[mt][1]), "=r"(af[mt][2]), "=r"(af[mt][3])
                    : "r"(a_addr));
            }
            int br = ks * 8 + (lane & 3);
            int bc = woffN + (lane >> 2);
            #pragma unroll
            for (int nt = 0; nt < 4; nt++) {
                const float* bb = bs + br * BS_STRIDE + bc + nt * 8;
                bf[nt][0] = __float_as_uint(bb[0]);
                bf[nt][1] = __float_as_uint(bb[4 * BS_STRIDE]);
            }
            #pragma unroll
            for (int mt = 0; mt < 4; mt++)
                #pragma unroll
                for (int nt = 0; nt < 4; nt++)
                    mma_tf32(c[mt][nt], af[mt], bf[nt]);
        }
    }

    #pragma unroll
    for (int mt = 0; mt < 4; mt++) {
        int r0 = mBase + woffM + mt * 16 + (lane >> 2);
        int r1 = r0 + 8;
        float g0 = bnp[r0], b0 = bnp[M + r0], m0 = bnp[2 * M + r0], v0 = bnp[3 * M + r0];
        float g1 = bnp[r1], b1 = bnp[M + r1], m1 = bnp[2 * M + r1], v1 = bnp[3 * M + r1];
        float inv0 = g0 * rsqrtf(v0 + 1e-5f), bias0 = b0 - m0 * inv0;
        float inv1 = g1 * rsqrtf(v1 + 1e-5f), bias1 = b1 - m1 * inv1;
        #pragma unroll
        for (int nt = 0; nt < 4; nt++) {
            int n = nBase + woffN + nt * 8 + 2 * (lane & 3);
            float2 o0, o1;
            o0.x = c[mt][nt][0] * inv0 + bias0;
            o0.y = c[mt][nt][1] * inv0 + bias0;
            o1.x = c[mt][nt][2] * inv1 + bias1;
            o1.y = c[mt][nt][3] * inv1 + bias1;
            *(float2*)(Yb + (size_t)r0 * NN + n) = o0;
            *(float2*)(Yb + (size_t)r1 * NN + n) = o1;
        }
    }
}

// ---------------- pooling ----------------------------------------------------
__global__ __launch_bounds__(256) void pool_kernel()
{
    int b = blockIdx.y, g = blockIdx.x, c = threadIdx.x;
    int gh = g >> 3, gw = g & 7;
    float s = 0.f;
    for (int hh = 0; hh < 8; hh++) {
        int h = gh * 8 + hh;
        for (int ww2 = 0; ww2 < 8; ww2++) {
            int w = gw * 8 + ww2;
            int flat = (h * Ww + w) * Cc + c;
            int nh = flat >> 17;
            int kd = (flat >> 12) & 31;
            int n  = flat & 4095;
            s += g_qkv[((size_t)(b * 768 + nh * 96 + kd)) * Nn + n];
        }
    }
    g_a[((b * NHh + (c >> 5)) * KDd + (c & 31)) * AGg + g] = s * (1.f / 64.f);
}

// ---------------- bilinear 7x7 -> 64x64 --------------------------------------
__device__ __forceinline__ float bilin7(const float* __restrict__ p, int oy, int ox)
{
    float uy = (oy + 0.5f) * (7.f / 64.f) - 0.5f;
    float ux = (ox + 0.5f) * (7.f / 64.f) - 0.5f;
    float fy = floorf(uy), fx = floorf(ux);
    int y0 = (int)fy, x0 = (int)fx;
    float ty = uy - fy, tx = ux - fx;
    int y0c = min(6, max(0, y0)),     y1c = min(6, max(0, y0 + 1));
    int x0c = min(6, max(0, x0)),     x1c = min(6, max(0, x0 + 1));
    float v00 = p[y0c * 7 + x0c], v01 = p[y0c * 7 + x1c];
    float v10 = p[y1c * 7 + x0c], v11 = p[y1c * 7 + x1c];
    return (v00 * (1.f - tx) + v01 * tx) * (1.f - ty)
         + (v10 * (1.f - tx) + v11 * tx) * ty;
}

// merged pb + ab
__global__ __launch_bounds__(256) void bias_kernel(
    const float* __restrict__ an, const float* __restrict__ ah, const float* __restrict__ aw,
    const float* __restrict__ na, const float* __restrict__ ha, const float* __restrict__ wa)
{
    int z = blockIdx.z, g = blockIdx.y;
    int n = blockIdx.x * 256 + threadIdx.x;
    int h = n >> 6, w = n & 63;
    if (z < 8) {
        int nh = z;
        float v = bilin7(an + (nh * AGg + g) * 49, h, w)
                + ah[(nh * AGg + g) * Hh + h] + aw[(nh * AGg + g) * Ww + w];
        g_pb[(size_t)(nh * AGg + g) * Nn + n] = v;
    } else {
        int nh = z - 8;
        float v = bilin7(na + (nh * AGg + g) * 49, h, w)
                + ha[(nh * Hh + h) * AGg + g] + wa[(nh * Ww + w) * AGg + g];
        g_ab[(size_t)(nh * AGg + g) * Nn + n] = v;
    }
}

// ---------------- attention-1 split: QK via mma.sync tf32 --------------------
__global__ __launch_bounds__(256) void attn1_split()
{
    int s = blockIdx.x;
    int bh = blockIdx.y; int b = bh >> 3, nh = bh & 7;
    __shared__ __align__(16) float aT_s[64][36];   // a^T[g][kd], tf32-rounded
    __shared__ __align__(16) float S[64][68];
    __shared__ float k_s[32][65];                  // tf32-rounded
    __shared__ float v_s[64][33];
    __shared__ float m_sh[64], l_sh[64], fact[64];
    int t = threadIdx.x;
    int lane = t & 31, wid = t >> 5;

    for (int i = t; i < 2048; i += 256) {
        int kd = i >> 6, g = i & 63;
        aT_s[g][kd] = __uint_as_float(f2tf32(g_a[((b * NHh + nh) * KDd) * AGg + i]));
    }
    if (t < 64) { m_sh[t] = -1e30f; l_sh[t] = 0.f; }
    __syncthreads();

    int woffG = (wid & 3) * 16;
    int woffN2 = (wid >> 2) * 32;

    uint32_t a_frag[4][4];
    #pragma unroll
    for (int ks = 0; ks < 4; ks++) {
        const float* ab = &aT_s[woffG + (lane >> 2)][ks * 8 + (lane & 3)];
        a_frag[ks][0] = __float_as_uint(ab[0]);
        a_frag[ks][1] = __float_as_uint(ab[8 * 36]);
        a_frag[ks][2] = __float_as_uint(ab[4]);
        a_frag[ks][3] = __float_as_uint(ab[8 * 36 + 4]);
    }

    const float* kbase = g_qkv + (size_t)(b * 768 + nh * 96 + 32) * Nn;
    const float* vbase = g_qkv + (size_t)(b * 768 + nh * 96 + 64) * Nn;
    const float* pbase = g_pb + (size_t)nh * AGg * Nn;
    const float scale = 0.17677669529663687f;

    float acc[8];
    #pragma unroll
    for (int j = 0; j < 8; j++) acc[j] = 0.f;

    int nStart = s * 1024, nEnd = nStart + 1024;

    for (int n0 = nStart; n0 < nEnd; n0 += 64) {
        for (int i = t; i < 2048; i += 256) {
            int ck = i >> 6, cn = i & 63;
            k_s[ck][cn] = __uint_as_float(f2tf32(kbase[(size_t)ck * Nn + n0 + cn]));
            v_s[cn][ck] = vbase[(size_t)ck * Nn + n0 + cn];
        }
        __syncthreads();

        {
            float c[4][4];
            #pragma unroll
            for (int nt = 0; nt < 4; nt++)
                #pragma unroll
                for (int r = 0; r < 4; r++) c[nt][r] = 0.f;
            #pragma unroll
            for (int ks = 0; ks < 4; ks++) {
                uint32_t bf[4][2];
                int br = ks * 8 + (lane & 3);
                int bc = woffN2 + (lane >> 2);
                #pragma unroll
                for (int nt = 0; nt < 4; nt++) {
                    bf[nt][0] = __float_as_uint(k_s[br][bc + nt * 8]);
                    bf[nt][1] = __float_as_uint(k_s[br + 4][bc + nt * 8]);
                }
                #pragma unroll
                for (int nt = 0; nt < 4; nt++)
                    mma_tf32(c[nt], a_frag[ks], bf[nt]);
            }
            int g0 = woffG + (lane >> 2);
            #pragma unroll
            for (int nt = 0; nt < 4; nt++) {
                int nl = woffN2 + nt * 8 + 2 * (lane & 3);
                *(float2*)&S[g0][nl]     = make_float2(c[nt][0], c[nt][1]);
                *(float2*)&S[g0 + 8][nl] = make_float2(c[nt][2], c[nt][3]);
            }
        }
        __syncthreads();

        #pragma unroll
        for (int j = 0; j < 8; j++) {
            int g = wid * 8 + j;
            const float* pbr = pbase + (size_t)g * Nn + n0;
            float v0 = S[g][lane] * scale + pbr[lane];
            float v1 = S[g][lane + 32] * scale + pbr[lane + 32];
            float mx = fmaxf(v0, v1);
            #pragma unroll
            for (int o = 16; o > 0; o >>= 1) mx = fmaxf(mx, __shfl_xor_sync(~0u, mx, o));
            float mold = m_sh[g];
            float mnew = fmaxf(mold, mx);
            float e0 = __expf(v0 - mnew), e1 = __expf(v1 - mnew);
            S[g][lane] = e0; S[g][lane + 32] = e1;
            float sum = e0 + e1;
            #pragma unroll
            for (int o = 16; o > 0; o >>= 1) sum += __shfl_xor_sync(~0u, sum, o);
            if (lane == 0) {
                float f = __expf(mold - mnew);
                l_sh[g] = l_sh[g] * f + sum;
                m_sh[g] = mnew;
                fact[g] = f;
            }
        }
        __syncthreads();

        {
            float a2[8];
            #pragma unroll
            for (int j = 0; j < 8; j++) a2[j] = acc[j] * fact[wid * 8 + j];
            #pragma unroll 4
            for (int nb = 0; nb < 64; nb += 4) {
                float vv0 = v_s[nb + 0][lane], vv1 = v_s[nb + 1][lane];
                float vv2 = v_s[nb + 2][lane], vv3 = v_s[nb + 3][lane];
                #pragma unroll
                for (int j = 0; j < 8; j++) {
                    float4 s4 = *(const float4*)&S[wid * 8 + j][nb];
                    a2[j] += s4.x * vv0 + s4.y * vv1 + s4.z * vv2 + s4.w * vv3;
                }
            }
            #pragma unroll
            for (int j = 0; j < 8; j++) acc[j] = a2[j];
        }
        __syncthreads();
    }
    #pragma unroll
    for (int j = 0; j < 8; j++) {
        int g = wid * 8 + j;
        int base = (bh * 4 + s) * AGg + g;
        g_p1acc[base * KDd + lane] = acc[j];
        if (lane == 0) { g_p1m[base] = m_sh[g]; g_p1l[base] = l_sh[g]; }
    }
}

// ---------------- attention-1 reduce over splits ------------------------------
__global__ __launch_bounds__(256) void attn1_reduce()
{
    int bh = blockIdx.x;
    int t = threadIdx.x;
    for (int i = t; i < AGg * KDd; i += 256) {
        int g = i >> 5, kd = i & 31;
        float m0 = g_p1m[(bh * 4 + 0) * AGg + g];
        float m1 = g_p1m[(bh * 4 + 1) * AGg + g];
        float m2 = g_p1m[(bh * 4 + 2) * AGg + g];
        float m3 = g_p1m[(bh * 4 + 3) * AGg + g];
        float M = fmaxf(fmaxf(m0, m1), fmaxf(m2, m3));
        float f0 = __expf(m0 - M), f1 = __expf(m1 - M);
        float f2 = __expf(m2 - M), f3 = __expf(m3 - M);
        float L = g_p1l[(bh * 4 + 0) * AGg + g] * f0
                + g_p1l[(bh * 4 + 1) * AGg + g] * f1
                + g_p1l[(bh * 4 + 2) * AGg + g] * f2
                + g_p1l[(bh * 4 + 3) * AGg + g] * f3;
        float V = g_p1acc[((bh * 4 + 0) * AGg + g) * KDd + kd] * f0
                + g_p1acc[((bh * 4 + 1) * AGg + g) * KDd + kd] * f1
                + g_p1acc[((bh * 4 + 2) * AGg + g) * KDd + kd] * f2
                + g_p1acc[((bh * 4 + 3) * AGg + g) * KDd + kd] * f3;
        g_attn[(bh * AGg + g) * KDd + kd] = V / L;
    }
}

// ------- fused attention-2 + depthwise pe conv + BN (R10 version) -------------
__global__ __launch_bounds__(128) void attn2_pe_kernel(
    const float* __restrict__ pw, const float* __restrict__ pebn)
{
    int b = blockIdx.z, nh = blockIdx.y;
    int n = blockIdx.x * 128 + threadIdx.x;
    int t = threadIdx.x;
    int h = n >> 6, w = n & 63;
    __shared__ __align__(16) float a_s[32][64];
    __shared__ __align__(16) float at_s[64][32];
    __shared__ float pw_s[32][9];
    __shared__ float inv_s[32], bias_s[32];
    for (int i = t; i < 2048; i += 128) {
        a_s[i >> 6][i & 63]  = g_a[((b * NHh + nh) * KDd) * AGg + i];
        at_s[i >> 5][i & 31] = g_attn[((b * NHh + nh) * AGg) * KDd + i];
    }
    for (int i = t; i < 288; i += 128)
        pw_s[i / 9][i % 9] = pw[(nh * 32) * 9 + i];
    if (t < 32) {
        int c = nh * 32 + t;
        float gg = pebn[c], bb = pebn[Cc + c], mm = pebn[2 * Cc + c], vv = pebn[3 * Cc + c];
        float inv = gg * rsqrtf(vv + 1e-5f);
        inv_s[t] = inv;
        bias_s[t] = bb - mm * inv;
    }
    __syncthreads();

    float msk[9];
    int off[9];
    {
        int j = 0;
        #pragma unroll
        for (int dy = -1; dy <= 1; dy++)
            #pragma unroll
            for (int dx = -1; dx <= 1; dx++, j++) {
                int hy = h + dy, wx = w + dx;
                bool ok = ((unsigned)hy < 64u) && ((unsigned)wx < 64u);
                msk[j] = ok ? 1.f : 0.f;
                off[j] = ok ? (dy * 64 + dx) : 0;
            }
    }

    const float scale = 0.17677669529663687f;
    float lg[64];
    #pragma unroll
    for (int g = 0; g < 64; g++) lg[g] = 0.f;
    {
        const float* qb = g_qkv + (size_t)(b * 768 + nh * 96) * Nn + n;
        #pragma unroll
        for (int kd = 0; kd < 32; kd++) {
            float qv = qb[(size_t)kd * Nn];
            const float4* arow = (const float4*)&a_s[kd][0];
            #pragma unroll
            for (int g4 = 0; g4 < 16; g4++) {
                float4 a4 = arow[g4];
                lg[g4 * 4 + 0] += qv * a4.x;
                lg[g4 * 4 + 1] += qv * a4.y;
                lg[g4 * 4 + 2] += qv * a4.z;
                lg[g4 * 4 + 3] += qv * a4.w;
            }
        }
    }
    #pragma unroll
    for (int g = 0; g < 64; g++)
        lg[g] = lg[g] * scale + g_ab[(size_t)(nh * AGg + g) * Nn + n];

    float mx = -1e30f;
    #pragma unroll
    for (int g = 0; g < 64; g++) mx = fmaxf(mx, lg[g]);
    float sum = 0.f;
    #pragma unroll
    for (int g = 0; g < 64; g++) { lg[g] = __expf(lg[g] - mx); sum += lg[g]; }
    float invs = 1.f / sum;

    float acc[32];
    #pragma unroll
    for (int kd = 0; kd < 32; kd++) acc[kd] = 0.f;
    #pragma unroll
    for (int g = 0; g < 64; g++) {
        float p = lg[g];
        const float4* trow = (const float4*)&at_s[g][0];
        #pragma unroll
        for (int k4 = 0; k4 < 8; k4++) {
            float4 t4 = trow[k4];
            acc[k4 * 4 + 0] += p * t4.x;
            acc[k4 * 4 + 1] += p * t4.y;
            acc[k4 * 4 + 2] += p * t4.z;
            acc[k4 * 4 + 3] += p * t4.w;
        }
    }

    const float* vhead = g_qkv + (size_t)(b * 768 + nh * 96 + 64) * Nn + n;
    #pragma unroll 4
    for (int kd = 0; kd < 32; kd++) {
        const float* vb = vhead + (size_t)kd * Nn;
        float conv = 0.f;
        #pragma unroll
        for (int j = 0; j < 9; j++)
            conv += msk[j] * vb[off[j]] * pw_s[kd][j];
        float o = acc[kd] * invs + conv * inv_s[kd] + bias_s[kd];
        g_out[((size_t)(b * Cc + nh * KDd + kd)) * Nn + n] =
            __uint_as_float(f2tf32(o));
    }
}

// -----------------------------------------------------------------------------
extern "C" void kernel_launch(void* const* d_in, const int* in_sizes, int n_in,
                              void* d_out, int out_size)
{
    const float* x       = (const float*)d_in[0];
    const float* qkv_w   = (const float*)d_in[1];
    const float* qkv_bn  = (const float*)d_in[2];
    const float* pe_w    = (const float*)d_in[3];
    const float* pe_bn   = (const float*)d_in[4];
    const float* proj_w  = (const float*)d_in[5];
    const float* proj_bn = (const float*)d_in[6];
    const float* an_bias = (const float*)d_in[7];
    const float* na_bias = (const float*)d_in[8];
    const float* ah_bias = (const float*)d_in[9];
    const float* aw_bias = (const float*)d_in[10];
    const float* ha_bias = (const float*)d_in[11];
    const float* wa_bias = (const float*)d_in[12];
    float* out = (float*)d_out;

    float *qkv_ptr, *out_ptr, *xr_ptr, *wq_ptr, *wp_ptr;
    cudaGetSymbolAddress((void**)&qkv_ptr, g_qkv);
    cudaGetSymbolAddress((void**)&out_ptr, g_out);
    cudaGetSymbolAddress((void**)&xr_ptr,  g_xr);
    cudaGetSymbolAddress((void**)&wq_ptr,  g_wq);
    cudaGetSymbolAddress((void**)&wp_ptr,  g_wp);

    cudaFuncSetAttribute(gemm_ca, cudaFuncAttributeMaxDynamicSharedMemorySize,
                         GEMM_SMEM);

    // 0. tf32 pre-rounding (rna) of GEMM inputs
    round_tf32_kernel<<<16384, 256>>>(x, xr_ptr, Bq * Cc * Nn);
    round_tf32_kernel<<<192, 256>>>(qkv_w, wq_ptr, 768 * 256);
    round_tf32_kernel<<<64, 256>>>(proj_w, wp_ptr, 256 * 256);

    // 1. qkv GEMM + BN
    gemm_ca<<<dim3(32, 6, 16), 256, GEMM_SMEM>>>(xr_ptr, wq_ptr, qkv_bn, qkv_ptr, 768, 256, 4096);
    // 2. pooling -> a
    pool_kernel<<<dim3(64, 16), 256>>>();
    // 3. bias maps (merged)
    bias_kernel<<<dim3(16, 64, 16), 256>>>(an_bias, ah_bias, aw_bias,
                                           na_bias, ha_bias, wa_bias);
    // 4. attention-1: split (QK via mma) + reduce
    attn1_split<<<dim3(4, 128), 256>>>();
    attn1_reduce<<<128, 256>>>();
    // 5. fused attention-2 + pe conv + BN
    attn2_pe_kernel<<<dim3(32, 8, 16), 128>>>(pe_w, pe_bn);
    // 6. proj GEMM + BN
    gemm_ca<<<dim3(32, 2, 16), 256, GEMM_SMEM>>>(out_ptr, wp_ptr, proj_bn, out, 256, 256, 4096);
}

// round 15
// speedup vs baseline: 1.5320x; 1.0590x over previous
#include <cuda_runtime.h>
#include <math.h>
#include <stdint.h>

#define Bq  16
#define Cc  256
#define NHh 8
#define KDd 32
#define Nn  4096
#define Hh  64
#define Ww  64
#define AGg 64

// ---------------- scratch (device globals; no allocation allowed) -----------
__device__ float g_qkv[(size_t)Bq * 768 * Nn];
__device__ float g_a[Bq * NHh * KDd * AGg];
__device__ float g_pb[NHh * AGg * Nn];
__device__ float g_ab[NHh * AGg * Nn];
__device__ float g_attn[Bq * NHh * AGg * KDd];
__device__ float g_out[(size_t)Bq * Cc * Nn];
__device__ __align__(256) float g_xr[(size_t)Bq * Cc * Nn];
__device__ __align__(256) float g_wq[768 * 256];
__device__ __align__(256) float g_wp[256 * 256];
__device__ float g_p1acc[128 * 4 * AGg * KDd];
__device__ float g_p1m[128 * 4 * AGg];
__device__ float g_p1l[128 * 4 * AGg];

__device__ __forceinline__ uint32_t f2tf32(float f) {
    uint32_t r;
    asm("cvt.rna.tf32.f32 %0, %1;" : "=r"(r) : "f"(f));
    return r;
}
__device__ __forceinline__ uint32_t smem_u32(const void* p) {
    uint32_t a;
    asm("{ .reg .u64 t; cvta.to.shared.u64 t, %1; cvt.u32.u64 %0, t; }"
        : "=r"(a) : "l"(p));
    return a;
}

// ---------------- tf32 pre-rounding pass (rna), float4 ----------------------
__global__ __launch_bounds__(256) void round_tf32_kernel(
    const float* __restrict__ in, float* __restrict__ out, int n)
{
    int i = (blockIdx.x * 256 + threadIdx.x) * 4;
    if (i >= n) return;
    float4 v = *(const float4*)(in + i);
    float4 o;
    o.x = __uint_as_float(f2tf32(v.x));
    o.y = __uint_as_float(f2tf32(v.y));
    o.z = __uint_as_float(f2tf32(v.z));
    o.w = __uint_as_float(f2tf32(v.w));
    *(float4*)(out + i) = o;
}

// ======================= tf32 mma.sync GEMM + BN (R10 config) ================
#define AS_STRIDE 36
#define BS_STRIDE 136
#define AFLOATS (128 * AS_STRIDE)
#define BFLOATS (32 * BS_STRIDE)
#define ABYTES (AFLOATS * 4)
#define STAGE_FLOATS (AFLOATS + BFLOATS)
#define STAGE_BYTES (STAGE_FLOATS * 4)
#define GEMM_SMEM (3 * STAGE_BYTES)

__device__ __forceinline__ void mma_tf32(float* c, const uint32_t* a, const uint32_t* b) {
    asm volatile(
        "mma.sync.aligned.m16n8k8.row.col.f32.tf32.tf32.f32 "
        "{%0,%1,%2,%3}, {%4,%5,%6,%7}, {%8,%9}, {%0,%1,%2,%3};"
        : "+f"(c[0]), "+f"(c[1]), "+f"(c[2]), "+f"(c[3])
        : "r"(a[0]), "r"(a[1]), "r"(a[2]), "r"(a[3]), "r"(b[0]), "r"(b[1]));
}

__global__ __launch_bounds__(256, 2) void gemm_ca(
    const float* __restrict__ X, const float* __restrict__ Wm,
    const float* __restrict__ bnp, float* __restrict__ Y,
    int M, int K, int NN)
{
    extern __shared__ float sm[];
    uint32_t sb = smem_u32(sm);
    int b = blockIdx.z, mBase = blockIdx.y * 128, nBase = blockIdx.x * 128;
    const float* Xb = X + (size_t)b * K * NN;
    float* Yb = Y + (size_t)b * M * NN;
    int tid = threadIdx.x, lane = tid & 31, wid = tid >> 5;
    int woffM = (wid >> 2) * 64, woffN = (wid & 3) * 32;

    int am = tid >> 1, ak = (tid & 1) * 16;
    int bk = tid >> 3, bn = (tid & 7) * 16;

    const float* wsrc0 = Wm + (size_t)(mBase + am) * K + ak;
    const float* xsrc0 = Xb + (size_t)bk * NN + nBase + bn;
    uint32_t adst_base = sb + (uint32_t)(am * AS_STRIDE + ak) * 4;
    uint32_t bdst_base = sb + ABYTES + (uint32_t)(bk * BS_STRIDE + bn) * 4;

    int lrow = lane & 15;
    int lcol = (lane >> 4) * 4;

    float c[4][4][4];
    #pragma unroll
    for (int mt = 0; mt < 4; mt++)
        #pragma unroll
        for (int nt = 0; nt < 4; nt++)
            #pragma unroll
            for (int r = 0; r < 4; r++) c[mt][nt][r] = 0.f;

    auto issue = [&](int ch, int buf) {
        const float* ws = wsrc0 + ch * 32;
        uint32_t ad = adst_base + buf * STAGE_BYTES;
        #pragma unroll
        for (int f = 0; f < 4; f++)
            asm volatile("cp.async.cg.shared.global [%0], [%1], 16;"
                :: "r"(ad + f * 16), "l"(ws + f * 4));
        const float* xs = xsrc0 + (size_t)(ch * 32) * NN;
        uint32_t bd = bdst_base + buf * STAGE_BYTES;
        #pragma unroll
        for (int f = 0; f < 4; f++)
            asm volatile("cp.async.cg.shared.global [%0], [%1], 16;"
                :: "r"(bd + f * 16), "l"(xs + f * 4));
        asm volatile("cp.async.commit_group;");
    };

    int nch = K >> 5;
    issue(0, 0);
    if (nch > 1) issue(1, 1);

    for (int ch = 0; ch < nch; ch++) {
        if (ch + 1 < nch) asm volatile("cp.async.wait_group 1;");
        else              asm volatile("cp.async.wait_group 0;");
        __syncthreads();
        if (ch + 2 < nch) issue(ch + 2, (ch + 2) % 3);

        uint32_t abase = sb + (ch % 3) * STAGE_BYTES;
        const float* bs = sm + (ch % 3) * STAGE_FLOATS + AFLOATS;

        #pragma unroll
        for (int ks = 0; ks < 4; ks++) {
            uint32_t af[4][4], bf[4][2];
            #pragma unroll
            for (int mt = 0; mt < 4; mt++) {
                uint32_t a_addr = abase +
                    (uint32_t)((woffM + mt * 16 + lrow) * AS_STRIDE + ks * 8 + lcol) * 4;
                asm volatile(
                    "ldmatrix.sync.aligned.m8n8.x4.shared.b16 {%0,%1,%2,%3}, [%4];"
                    : "=r"(af[mt][0]), "=r"(af[mt][1]), "=r"(af[mt][2]), "=r"(af[mt][3])
                    : "r"(a_addr));
            }
            int br = ks * 8 + (lane & 3);
            int bc = woffN + (lane >> 2);
            #pragma unroll
            for (int nt = 0; nt < 4; nt++) {
                const float* bb = bs + br * BS_STRIDE + bc + nt * 8;
                bf[nt][0] = __float_as_uint(bb[0]);
                bf[nt][1] = __float_as_uint(bb[4 * BS_STRIDE]);
            }
            #pragma unroll
            for (int mt = 0; mt < 4; mt++)
                #pragma unroll
                for (int nt = 0; nt < 4; nt++)
                    mma_tf32(c[mt][nt], af[mt], bf[nt]);
        }
    }

    #pragma unroll
    for (int mt = 0; mt < 4; mt++) {
        int r0 = mBase + woffM + mt * 16 + (lane >> 2);
        int r1 = r0 + 8;
        float g0 = bnp[r0], b0 = bnp[M + r0], m0 = bnp[2 * M + r0], v0 = bnp[3 * M + r0];
        float g1 = bnp[r1], b1 = bnp[M + r1], m1 = bnp[2 * M + r1], v1 = bnp[3 * M + r1];
        float inv0 = g0 * rsqrtf(v0 + 1e-5f), bias0 = b0 - m0 * inv0;
        float inv1 = g1 * rsqrtf(v1 + 1e-5f), bias1 = b1 - m1 * inv1;
        #pragma unroll
        for (int nt = 0; nt < 4; nt++) {
            int n = nBase + woffN + nt * 8 + 2 * (lane & 3);
            float2 o0, o1;
            o0.x = c[mt][nt][0] * inv0 + bias0;
            o0.y = c[mt][nt][1] * inv0 + bias0;
            o1.x = c[mt][nt][2] * inv1 + bias1;
            o1.y = c[mt][nt][3] * inv1 + bias1;
            *(float2*)(Yb + (size_t)r0 * NN + n) = o0;
            *(float2*)(Yb + (size_t)r1 * NN + n) = o1;
        }
    }
}

// ---------------- pooling ----------------------------------------------------
__global__ __launch_bounds__(256) void pool_kernel()
{
    int b = blockIdx.y, g = blockIdx.x, c = threadIdx.x;
    int gh = g >> 3, gw = g & 7;
    float s = 0.f;
    for (int hh = 0; hh < 8; hh++) {
        int h = gh * 8 + hh;
        for (int ww2 = 0; ww2 < 8; ww2++) {
            int w = gw * 8 + ww2;
            int flat = (h * Ww + w) * Cc + c;
            int nh = flat >> 17;
            int kd = (flat >> 12) & 31;
            int n  = flat & 4095;
            s += g_qkv[((size_t)(b * 768 + nh * 96 + kd)) * Nn + n];
        }
    }
    g_a[((b * NHh + (c >> 5)) * KDd + (c & 31)) * AGg + g] = s * (1.f / 64.f);
}

// ---------------- bilinear 7x7 -> 64x64 --------------------------------------
__device__ __forceinline__ float bilin7(const float* __restrict__ p, int oy, int ox)
{
    float uy = (oy + 0.5f) * (7.f / 64.f) - 0.5f;
    float ux = (ox + 0.5f) * (7.f / 64.f) - 0.5f;
    float fy = floorf(uy), fx = floorf(ux);
    int y0 = (int)fy, x0 = (int)fx;
    float ty = uy - fy, tx = ux - fx;
    int y0c = min(6, max(0, y0)),     y1c = min(6, max(0, y0 + 1));
    int x0c = min(6, max(0, x0)),     x1c = min(6, max(0, x0 + 1));
    float v00 = p[y0c * 7 + x0c], v01 = p[y0c * 7 + x1c];
    float v10 = p[y1c * 7 + x0c], v11 = p[y1c * 7 + x1c];
    return (v00 * (1.f - tx) + v01 * tx) * (1.f - ty)
         + (v10 * (1.f - tx) + v11 * tx) * ty;
}

// merged pb + ab
__global__ __launch_bounds__(256) void bias_kernel(
    const float* __restrict__ an, const float* __restrict__ ah, const float* __restrict__ aw,
    const float* __restrict__ na, const float* __restrict__ ha, const float* __restrict__ wa)
{
    int z = blockIdx.z, g = blockIdx.y;
    int n = blockIdx.x * 256 + threadIdx.x;
    int h = n >> 6, w = n & 63;
    if (z < 8) {
        int nh = z;
        float v = bilin7(an + (nh * AGg + g) * 49, h, w)
                + ah[(nh * AGg + g) * Hh + h] + aw[(nh * AGg + g) * Ww + w];
        g_pb[(size_t)(nh * AGg + g) * Nn + n] = v;
    } else {
        int nh = z - 8;
        float v = bilin7(na + (nh * AGg + g) * 49, h, w)
                + ha[(nh * Hh + h) * AGg + g] + wa[(nh * Ww + w) * AGg + g];
        g_ab[(size_t)(nh * AGg + g) * Nn + n] = v;
    }
}

// ------- attention-1 split: QK AND PV via mma.sync tf32 -----------------------
// 256 threads, 8 warps.
// QK warp layout: warp w -> g rows (w&3)*16..+15, n cols (w>>2)*32..+31
// PV warp layout: warp w -> g rows (w&3)*16..+15, kd cols (w>>2)*16..+15
__global__ __launch_bounds__(256) void attn1_split()
{
    int s = blockIdx.x;
    int bh = blockIdx.y; int b = bh >> 3, nh = bh & 7;
    __shared__ __align__(16) float aT_s[64][36];   // a^T[g][kd], tf32
    __shared__ __align__(16) float S[64][68];      // logits -> tf32 probs
    __shared__ __align__(16) float k_s[32][65];    // tf32
    __shared__ __align__(16) float v_s[64][40];    // v[n][kd], tf32
    __shared__ float m_sh[64], l_sh[64], fact[64];
    int t = threadIdx.x;
    int lane = t & 31, wid = t >> 5;
    uint32_t S_base = smem_u32(&S[0][0]);

    for (int i = t; i < 2048; i += 256) {
        int kd = i >> 6, g = i & 63;
        aT_s[g][kd] = __uint_as_float(f2tf32(g_a[((b * NHh + nh) * KDd) * AGg + i]));
    }
    if (t < 64) { m_sh[t] = -1e30f; l_sh[t] = 0.f; }
    __syncthreads();

    int lrow = lane & 15;
    int lcol = (lane >> 4) * 4;
    int woffG  = (wid & 3) * 16;    // shared by QK and PV layouts
    int woffN2 = (wid >> 2) * 32;   // QK n-tile
    int woffKD = (wid >> 2) * 16;   // PV kd-tile

    // QK A fragments (loop-invariant)
    uint32_t a_frag[4][4];
    #pragma unroll
    for (int ks = 0; ks < 4; ks++) {
        const float* ab = &aT_s[woffG + (lane >> 2)][ks * 8 + (lane & 3)];
        a_frag[ks][0] = __float_as_uint(ab[0]);
        a_frag[ks][1] = __float_as_uint(ab[8 * 36]);
        a_frag[ks][2] = __float_as_uint(ab[4]);
        a_frag[ks][3] = __float_as_uint(ab[8 * 36 + 4]);
    }

    const float* kbase = g_qkv + (size_t)(b * 768 + nh * 96 + 32) * Nn;
    const float* vbase = g_qkv + (size_t)(b * 768 + nh * 96 + 64) * Nn;
    const float* pbase = g_pb + (size_t)nh * AGg * Nn;
    const float scale = 0.17677669529663687f;

    // PV accumulators (fragment layout, fp32, persist across chunks)
    float cpv[2][4];
    #pragma unroll
    for (int nt = 0; nt < 2; nt++)
        #pragma unroll
        for (int r = 0; r < 4; r++) cpv[nt][r] = 0.f;

    int nStart = s * 1024, nEnd = nStart + 1024;

    for (int n0 = nStart; n0 < nEnd; n0 += 64) {
        for (int i = t; i < 2048; i += 256) {
            int ck = i >> 6, cn = i & 63;
            k_s[ck][cn] = __uint_as_float(f2tf32(kbase[(size_t)ck * Nn + n0 + cn]));
            v_s[cn][ck] = __uint_as_float(f2tf32(vbase[(size_t)ck * Nn + n0 + cn]));
        }
        __syncthreads();

        // ---- QK logits via mma: S_tile[16g x 32n] per warp
        {
            float c[4][4];
            #pragma unroll
            for (int nt = 0; nt < 4; nt++)
                #pragma unroll
                for (int r = 0; r < 4; r++) c[nt][r] = 0.f;
            #pragma unroll
            for (int ks = 0; ks < 4; ks++) {
                uint32_t bf[4][2];
                int br = ks * 8 + (lane & 3);
                int bc = woffN2 + (lane >> 2);
                #pragma unroll
                for (int nt = 0; nt < 4; nt++) {
                    bf[nt][0] = __float_as_uint(k_s[br][bc + nt * 8]);
                    bf[nt][1] = __float_as_uint(k_s[br + 4][bc + nt * 8]);
                }
                #pragma unroll
                for (int nt = 0; nt < 4; nt++)
                    mma_tf32(c[nt], a_frag[ks], bf[nt]);
            }
            int g0 = woffG + (lane >> 2);
            #pragma unroll
            for (int nt = 0; nt < 4; nt++) {
                int nl = woffN2 + nt * 8 + 2 * (lane & 3);
                *(float2*)&S[g0][nl]     = make_float2(c[nt][0], c[nt][1]);
                *(float2*)&S[g0 + 8][nl] = make_float2(c[nt][2], c[nt][3]);
            }
        }
        __syncthreads();

        // ---- online softmax: writes tf32-rounded probs into S
        #pragma unroll
        for (int j = 0; j < 8; j++) {
            int g = wid * 8 + j;
            const float* pbr = pbase + (size_t)g * Nn + n0;
            float v0 = S[g][lane] * scale + pbr[lane];
            float v1 = S[g][lane + 32] * scale + pbr[lane + 32];
            float mx = fmaxf(v0, v1);
            #pragma unroll
            for (int o = 16; o > 0; o >>= 1) mx = fmaxf(mx, __shfl_xor_sync(~0u, mx, o));
            float mold = m_sh[g];
            float mnew = fmaxf(mold, mx);
            float e0 = __expf(v0 - mnew), e1 = __expf(v1 - mnew);
            S[g][lane]      = __uint_as_float(f2tf32(e0));
            S[g][lane + 32] = __uint_as_float(f2tf32(e1));
            float sum = e0 + e1;
            #pragma unroll
            for (int o = 16; o > 0; o >>= 1) sum += __shfl_xor_sync(~0u, sum, o);
            if (lane == 0) {
                float f = __expf(mold - mnew);
                l_sh[g] = l_sh[g] * f + sum;
                m_sh[g] = mnew;
                fact[g] = f;
            }
        }
        __syncthreads();

        // ---- PV via mma: O_tile[16g x 16kd] per warp, rescale then accumulate
        {
            float f0v = fact[woffG + (lane >> 2)];
            float f1v = fact[woffG + (lane >> 2) + 8];
            #pragma unroll
            for (int nt = 0; nt < 2; nt++) {
                cpv[nt][0] *= f0v; cpv[nt][1] *= f0v;
                cpv[nt][2] *= f1v; cpv[nt][3] *= f1v;
            }
            #pragma unroll
            for (int ks = 0; ks < 8; ks++) {
                uint32_t afp[4];
                uint32_t s_addr = S_base +
                    (uint32_t)((woffG + lrow) * 68 + ks * 8 + lcol) * 4;
                asm volatile(
                    "ldmatrix.sync.aligned.m8n8.x4.shared.b16 {%0,%1,%2,%3}, [%4];"
                    : "=r"(afp[0]), "=r"(afp[1]), "=r"(afp[2]), "=r"(afp[3])
                    : "r"(s_addr));
                int br = ks * 8 + (lane & 3);
                int bc = woffKD + (lane >> 2);
                uint32_t bf0[2], bf1[2];
                bf0[0] = __float_as_uint(v_s[br][bc]);
                bf0[1] = __float_as_uint(v_s[br + 4][bc]);
                bf1[0] = __float_as_uint(v_s[br][bc + 8]);
                bf1[1] = __float_as_uint(v_s[br + 4][bc + 8]);
                mma_tf32(cpv[0], afp, bf0);
                mma_tf32(cpv[1], afp, bf1);
            }
        }
        __syncthreads();
    }

    // ---- store partials (fragment layout)
    int base0 = (bh * 4 + s) * AGg;
    int g0 = woffG + (lane >> 2);
    #pragma unroll
    for (int nt = 0; nt < 2; nt++) {
        int kd = woffKD + nt * 8 + 2 * (lane & 3);
        *(float2*)&g_p1acc[(base0 + g0) * KDd + kd]     = make_float2(cpv[nt][0], cpv[nt][1]);
        *(float2*)&g_p1acc[(base0 + g0 + 8) * KDd + kd] = make_float2(cpv[nt][2], cpv[nt][3]);
    }
    if (t < 64) { g_p1m[base0 + t] = m_sh[t]; g_p1l[base0 + t] = l_sh[t]; }
}

// ---------------- attention-1 reduce over splits ------------------------------
__global__ __launch_bounds__(256) void attn1_reduce()
{
    int bh = blockIdx.x;
    int t = threadIdx.x;
    for (int i = t; i < AGg * KDd; i += 256) {
        int g = i >> 5, kd = i & 31;
        float m0 = g_p1m[(bh * 4 + 0) * AGg + g];
        float m1 = g_p1m[(bh * 4 + 1) * AGg + g];
        float m2 = g_p1m[(bh * 4 + 2) * AGg + g];
        float m3 = g_p1m[(bh * 4 + 3) * AGg + g];
        float M = fmaxf(fmaxf(m0, m1), fmaxf(m2, m3));
        float f0 = __expf(m0 - M), f1 = __expf(m1 - M);
        float f2 = __expf(m2 - M), f3 = __expf(m3 - M);
        float L = g_p1l[(bh * 4 + 0) * AGg + g] * f0
                + g_p1l[(bh * 4 + 1) * AGg + g] * f1
                + g_p1l[(bh * 4 + 2) * AGg + g] * f2
                + g_p1l[(bh * 4 + 3) * AGg + g] * f3;
        float V = g_p1acc[((bh * 4 + 0) * AGg + g) * KDd + kd] * f0
                + g_p1acc[((bh * 4 + 1) * AGg + g) * KDd + kd] * f1
                + g_p1acc[((bh * 4 + 2) * AGg + g) * KDd + kd] * f2
                + g_p1acc[((bh * 4 + 3) * AGg + g) * KDd + kd] * f3;
        g_attn[(bh * AGg + g) * KDd + kd] = V / L;
    }
}

// ------- fused attention-2 + depthwise pe conv + BN ---------------------------
__global__ __launch_bounds__(128) void attn2_pe_kernel(
    const float* __restrict__ pw, const float* __restrict__ pebn)
{
    int b = blockIdx.z, nh = blockIdx.y;
    int n = blockIdx.x * 128 + threadIdx.x;
    int t = threadIdx.x;
    int h = n >> 6, w = n & 63;
    __shared__ __align__(16) float a_s[32][64];
    __shared__ __align__(16) float at_s[64][32];
    __shared__ float pw_s[32][9];
    __shared__ float inv_s[32], bias_s[32];
    for (int i = t; i < 2048; i += 128) {
        a_s[i >> 6][i & 63]  = g_a[((b * NHh + nh) * KDd) * AGg + i];
        at_s[i >> 5][i & 31] = g_attn[((b * NHh + nh) * AGg) * KDd + i];
    }
    for (int i = t; i < 288; i += 128)
        pw_s[i / 9][i % 9] = pw[(nh * 32) * 9 + i];
    if (t < 32) {
        int c = nh * 32 + t;
        float gg = pebn[c], bb = pebn[Cc + c], mm = pebn[2 * Cc + c], vv = pebn[3 * Cc + c];
        float inv = gg * rsqrtf(vv + 1e-5f);
        inv_s[t] = inv;
        bias_s[t] = bb - mm * inv;
    }
    __syncthreads();

    float msk[9];
    int off[9];
    {
        int j = 0;
        #pragma unroll
        for (int dy = -1; dy <= 1; dy++)
            #pragma unroll
            for (int dx = -1; dx <= 1; dx++, j++) {
                int hy = h + dy, wx = w + dx;
                bool ok = ((unsigned)hy < 64u) && ((unsigned)wx < 64u);
                msk[j] = ok ? 1.f : 0.f;
                off[j] = ok ? (dy * 64 + dx) : 0;
            }
    }

    const float scale = 0.17677669529663687f;
    float lg[64];
    #pragma unroll
    for (int g = 0; g < 64; g++) lg[g] = 0.f;
    {
        const float* qb = g_qkv + (size_t)(b * 768 + nh * 96) * Nn + n;
        #pragma unroll
        for (int kd = 0; kd < 32; kd++) {
            float qv = qb[(size_t)kd * Nn];
            const float4* arow = (const float4*)&a_s[kd][0];
            #pragma unroll
            for (int g4 = 0; g4 < 16; g4++) {
                float4 a4 = arow[g4];
                lg[g4 * 4 + 0] += qv * a4.x;
                lg[g4 * 4 + 1] += qv * a4.y;
                lg[g4 * 4 + 2] += qv * a4.z;
                lg[g4 * 4 + 3] += qv * a4.w;
            }
        }
    }
    #pragma unroll
    for (int g = 0; g < 64; g++)
        lg[g] = lg[g] * scale + g_ab[(size_t)(nh * AGg + g) * Nn + n];

    float mx = -1e30f;
    #pragma unroll
    for (int g = 0; g < 64; g++) mx = fmaxf(mx, lg[g]);
    float sum = 0.f;
    #pragma unroll
    for (int g = 0; g < 64; g++) { lg[g] = __expf(lg[g] - mx); sum += lg[g]; }
    float invs = 1.f / sum;

    float acc[32];
    #pragma unroll
    for (int kd = 0; kd < 32; kd++) acc[kd] = 0.f;
    #pragma unroll
    for (int g = 0; g < 64; g++) {
        float p = lg[g];
        const float4* trow = (const float4*)&at_s[g][0];
        #pragma unroll
        for (int k4 = 0; k4 < 8; k4++) {
            float4 t4 = trow[k4];
            acc[k4 * 4 + 0] += p * t4.x;
            acc[k4 * 4 + 1] += p * t4.y;
            acc[k4 * 4 + 2] += p * t4.z;
            acc[k4 * 4 + 3] += p * t4.w;
        }
    }

    const float* vhead = g_qkv + (size_t)(b * 768 + nh * 96 + 64) * Nn + n;
    #pragma unroll 4
    for (int kd = 0; kd < 32; kd++) {
        const float* vb = vhead + (size_t)kd * Nn;
        float conv = 0.f;
        #pragma unroll
        for (int j = 0; j < 9; j++)
            conv += msk[j] * vb[off[j]] * pw_s[kd][j];
        float o = acc[kd] * invs + conv * inv_s[kd] + bias_s[kd];
        g_out[((size_t)(b * Cc + nh * KDd + kd)) * Nn + n] =
            __uint_as_float(f2tf32(o));
    }
}

// -----------------------------------------------------------------------------
extern "C" void kernel_launch(void* const* d_in, const int* in_sizes, int n_in,
                              void* d_out, int out_size)
{
    const float* x       = (const float*)d_in[0];
    const float* qkv_w   = (const float*)d_in[1];
    const float* qkv_bn  = (const float*)d_in[2];
    const float* pe_w    = (const float*)d_in[3];
    const float* pe_bn   = (const float*)d_in[4];
    const float* proj_w  = (const float*)d_in[5];
    const float* proj_bn = (const float*)d_in[6];
    const float* an_bias = (const float*)d_in[7];
    const float* na_bias = (const float*)d_in[8];
    const float* ah_bias = (const float*)d_in[9];
    const float* aw_bias = (const float*)d_in[10];
    const float* ha_bias = (const float*)d_in[11];
    const float* wa_bias = (const float*)d_in[12];
    float* out = (float*)d_out;

    float *qkv_ptr, *out_ptr, *xr_ptr, *wq_ptr, *wp_ptr;
    cudaGetSymbolAddress((void**)&qkv_ptr, g_qkv);
    cudaGetSymbolAddress((void**)&out_ptr, g_out);
    cudaGetSymbolAddress((void**)&xr_ptr,  g_xr);
    cudaGetSymbolAddress((void**)&wq_ptr,  g_wq);
    cudaGetSymbolAddress((void**)&wp_ptr,  g_wp);

    cudaFuncSetAttribute(gemm_ca, cudaFuncAttributeMaxDynamicSharedMemorySize,
                         GEMM_SMEM);

    // 0. tf32 pre-rounding (rna) of GEMM inputs
    round_tf32_kernel<<<16384, 256>>>(x, xr_ptr, Bq * Cc * Nn);
    round_tf32_kernel<<<192, 256>>>(qkv_w, wq_ptr, 768 * 256);
    round_tf32_kernel<<<64, 256>>>(proj_w, wp_ptr, 256 * 256);

    // 1. qkv GEMM + BN
    gemm_ca<<<dim3(32, 6, 16), 256, GEMM_SMEM>>>(xr_ptr, wq_ptr, qkv_bn, qkv_ptr, 768, 256, 4096);
    // 2. pooling -> a
    pool_kernel<<<dim3(64, 16), 256>>>();
    // 3. bias maps (merged)
    bias_kernel<<<dim3(16, 64, 16), 256>>>(an_bias, ah_bias, aw_bias,
                                           na_bias, ha_bias, wa_bias);
    // 4. attention-1: split (QK + PV via mma) + reduce
    attn1_split<<<dim3(4, 128), 256>>>();
    attn1_reduce<<<128, 256>>>();
    // 5. fused attention-2 + pe conv + BN
    attn2_pe_kernel<<<dim3(32, 8, 16), 128>>>(pe_w, pe_bn);
    // 6. proj GEMM + BN
    gemm_ca<<<dim3(32, 2, 16), 256, GEMM_SMEM>>>(out_ptr, wp_ptr, proj_bn, out, 256, 256, 4096);
}